// round 4
// baseline (speedup 1.0000x reference)
#include <cuda_runtime.h>

// LDDMM Hamiltonian evolve, B=1, N=8192, D=3, sigma=0.1
// out[0 : 3N]   = -dH/dq = 400 * sum_j K_ij * <p_i,p_j> * (q_i - q_j)
// out[3N : 6N]  =  dH/dp = 2   * sum_j K_ij * p_j
// K_ij = exp(-100*|q_i-q_j|^2) = exp2(C*d2), C = -100*log2(e)
//
// d2 expanded via norms (coords centered at 0.5):
//   K_ij = E_i * exp2( s_j + cq_j . m2q_i ),  E_i = exp2(C*|cq_i|^2)
// 14 packed f32x2 fma-pipe ops per 2 j-points. Single fused kernel:
// last CTA of each i-group (16 js-partials) reduces and writes out.

#define NPTS 8192
#define TI 128             // threads per CTA (i-tile)
#define JSPLIT 16          // j-dimension partitions
#define JC (NPTS / JSPLIT) // 512 j per CTA
#define JPAIRS (JC / 2)    // 256 packed pairs
#define HALFSZ (NPTS * 3)  // floats per output half
#define NGROUP (NPTS / TI) // 64 i-groups

// Scratch: [JSPLIT][NPTS][8] (a0,a1,a2,b0,b1,b2,pad,pad) — 4 MB
__device__ float g_part[(size_t)JSPLIT * NPTS * 8];
// Persistent arrival counters per i-group (modulo-JSPLIT trick: no reset needed)
__device__ unsigned int g_cnt[NGROUP];

typedef unsigned long long u64;

__device__ __forceinline__ u64 pack2(float lo, float hi) {
    u64 r; asm("mov.b64 %0, {%1, %2};" : "=l"(r) : "f"(lo), "f"(hi)); return r;
}
__device__ __forceinline__ void unpack2(u64 v, float& lo, float& hi) {
    asm("mov.b64 {%0, %1}, %2;" : "=f"(lo), "=f"(hi) : "l"(v));
}
__device__ __forceinline__ u64 fma2(u64 a, u64 b, u64 c) {
    u64 r; asm("fma.rn.f32x2 %0, %1, %2, %3;" : "=l"(r) : "l"(a), "l"(b), "l"(c)); return r;
}
__device__ __forceinline__ u64 add2(u64 a, u64 b) {
    u64 r; asm("add.rn.f32x2 %0, %1, %2;" : "=l"(r) : "l"(a), "l"(b)); return r;
}
__device__ __forceinline__ u64 mul2(u64 a, u64 b) {
    u64 r; asm("mul.rn.f32x2 %0, %1, %2;" : "=l"(r) : "l"(a), "l"(b)); return r;
}
__device__ __forceinline__ u64 ex2_2(u64 x) {
    u64 r;
    asm("{\n\t"
        ".reg .f32 l, h;\n\t"
        "mov.b64 {l, h}, %1;\n\t"
        "ex2.approx.ftz.f32 l, l;\n\t"
        "ex2.approx.ftz.f32 h, h;\n\t"
        "mov.b64 %0, {l, h};\n\t"
        "}" : "=l"(r) : "l"(x));
    return r;
}
__device__ __forceinline__ float fast_ex2(float x) {
    float y; asm("ex2.approx.ftz.f32 %0, %1;" : "=f"(y) : "f"(x)); return y;
}

#define CKER (-144.26950408889634f)   // -100 * log2(e)

__global__ __launch_bounds__(TI, 8)
void lddmm_fused_kernel(const float* __restrict__ mom,
                        const float* __restrict__ q,
                        float* __restrict__ out) {
    // Per j-pair: 6 packed u64: [cqx|cqy|cqz|sj|pjx|pjy] + [pjz ...] layout:
    // [cqx, cqy, cqz, sj, pjx, pjy, pjz -> packed into 6 u64? need 7 slots]
    // Slots: 0:cqx 1:cqy 2:cqz 3:sj 4:pjx 5:pjy ... pjz goes where?
    // Use 6 u64 = [cqx|cqy|cqz|sj|pjx|pjy] won't fit pjz. Keep 8-slot? No:
    // reorder as three 16B groups: (cqx,cqy) (cqz,sj) (pjx,pjy) + pjz separate.
    // -> store pjz in a parallel array region to keep 3x LDS.128 + 1 LDS.64.
    // Simpler: keep 6 u64 with [cqx|cqy][cqz|sj][pjx|pjy] as 3x v2 and pjz
    // in a second array (still broadcast, conflict-free).
    __shared__ __align__(16) u64 s[JPAIRS * 6];
    __shared__ __align__(16) u64 sz[JPAIRS];
    __shared__ bool s_last;

    const int bi = blockIdx.x;
    const int js = blockIdx.y;
    const int jbase = js * JC;

    for (int p = threadIdx.x; p < JPAIRS; p += TI) {
        const int j0 = jbase + 2 * p;
        const int j1 = j0 + 1;
        const float x0 = q[j0 * 3 + 0] - 0.5f, x1 = q[j1 * 3 + 0] - 0.5f;
        const float y0 = q[j0 * 3 + 1] - 0.5f, y1 = q[j1 * 3 + 1] - 0.5f;
        const float z0 = q[j0 * 3 + 2] - 0.5f, z1 = q[j1 * 3 + 2] - 0.5f;
        const float s0 = CKER * (x0 * x0 + y0 * y0 + z0 * z0);
        const float s1 = CKER * (x1 * x1 + y1 * y1 + z1 * z1);
        s[p * 6 + 0] = pack2(x0, x1);
        s[p * 6 + 1] = pack2(y0, y1);
        s[p * 6 + 2] = pack2(z0, z1);
        s[p * 6 + 3] = pack2(s0, s1);
        s[p * 6 + 4] = pack2(mom[j0 * 3 + 0], mom[j1 * 3 + 0]);
        s[p * 6 + 5] = pack2(mom[j0 * 3 + 1], mom[j1 * 3 + 1]);
        sz[p]        = pack2(mom[j0 * 3 + 2], mom[j1 * 3 + 2]);
    }
    __syncthreads();

    const int i = bi * TI + threadIdx.x;
    const float cqx = q[i * 3 + 0] - 0.5f;
    const float cqy = q[i * 3 + 1] - 0.5f;
    const float cqz = q[i * 3 + 2] - 0.5f;
    const float px = mom[i * 3 + 0], py = mom[i * 3 + 1], pz = mom[i * 3 + 2];

    const float m2x = -2.0f * CKER * cqx;
    const float m2y = -2.0f * CKER * cqy;
    const float m2z = -2.0f * CKER * cqz;
    const u64 M2X = pack2(m2x, m2x), M2Y = pack2(m2y, m2y), M2Z = pack2(m2z, m2z);
    const u64 PXX = pack2(px, px), PYY = pack2(py, py), PZZ = pack2(pz, pz);

    u64 B0 = 0, B1 = 0, B2 = 0;  // sum K' * p_j
    u64 A0 = 0, A1 = 0, A2 = 0;  // sum w' * cq_j
    u64 W  = 0;                   // sum w'

#pragma unroll 4
    for (int p = 0; p < JPAIRS; p++) {
        const ulonglong2 w0 = *reinterpret_cast<const ulonglong2*>(&s[p * 6 + 0]);
        const ulonglong2 w1 = *reinterpret_cast<const ulonglong2*>(&s[p * 6 + 2]);
        const ulonglong2 w2 = *reinterpret_cast<const ulonglong2*>(&s[p * 6 + 4]);
        const u64 mz = sz[p];
        const u64 jx = w0.x, jy = w0.y, jz = w1.x, sj = w1.y;
        const u64 mx = w2.x, my = w2.y;

        u64 t = fma2(jx, M2X, sj);
        t = fma2(jy, M2Y, t);
        t = fma2(jz, M2Z, t);
        const u64 K = ex2_2(t);

        const u64 pd = fma2(PXX, mx, fma2(PYY, my, mul2(PZZ, mz)));

        B0 = fma2(K, mx, B0);
        B1 = fma2(K, my, B1);
        B2 = fma2(K, mz, B2);

        const u64 w = mul2(K, pd);
        W  = add2(W, w);
        A0 = fma2(w, jx, A0);
        A1 = fma2(w, jy, A1);
        A2 = fma2(w, jz, A2);
    }

    // Epilogue: fold E_i and output scales; write partial record.
    const float Ei = fast_ex2(CKER * (cqx * cqx + cqy * cqy + cqz * cqz));
    const float eq = 400.0f * Ei;
    const float ep = 2.0f * Ei;

    float l, h, Ws, A0s, A1s, A2s, B0s, B1s, B2s;
    unpack2(W,  l, h); Ws  = l + h;
    unpack2(A0, l, h); A0s = l + h;
    unpack2(A1, l, h); A1s = l + h;
    unpack2(A2, l, h); A2s = l + h;
    unpack2(B0, l, h); B0s = l + h;
    unpack2(B1, l, h); B1s = l + h;
    unpack2(B2, l, h); B2s = l + h;

    float4* rec = reinterpret_cast<float4*>(&g_part[(((size_t)js * NPTS) + i) * 8]);
    rec[0] = make_float4(eq * fmaf(Ws, cqx, -A0s),
                         eq * fmaf(Ws, cqy, -A1s),
                         eq * fmaf(Ws, cqz, -A2s),
                         0.0f);
    rec[1] = make_float4(ep * B0s, ep * B1s, ep * B2s, 0.0f);

    // Publish, then count arrivals for this i-group.
    __threadfence();
    __syncthreads();
    if (threadIdx.x == 0) {
        unsigned int old = atomicAdd(&g_cnt[bi], 1u);
        s_last = (((old + 1) & (JSPLIT - 1)) == 0);
    }
    __syncthreads();

    if (s_last) {
        __threadfence();  // order our reads after the arrival atomic
        float a0 = 0.f, a1 = 0.f, a2 = 0.f, b0 = 0.f, b1 = 0.f, b2 = 0.f;
#pragma unroll
        for (int k = 0; k < JSPLIT; k++) {
            const float4* r = reinterpret_cast<const float4*>(
                &g_part[(((size_t)k * NPTS) + i) * 8]);
            const float4 ra = r[0];
            const float4 rb = r[1];
            a0 += ra.x; a1 += ra.y; a2 += ra.z;
            b0 += rb.x; b1 += rb.y; b2 += rb.z;
        }
        out[i * 3 + 0] = a0;
        out[i * 3 + 1] = a1;
        out[i * 3 + 2] = a2;
        out[HALFSZ + i * 3 + 0] = b0;
        out[HALFSZ + i * 3 + 1] = b1;
        out[HALFSZ + i * 3 + 2] = b2;
    }
}

extern "C" void kernel_launch(void* const* d_in, const int* in_sizes, int n_in,
                              void* d_out, int out_size) {
    const float* mom = (const float*)d_in[0];            // [1,8192,3]
    const float* control_points = (const float*)d_in[1]; // [1,8192,3]
    float* out = (float*)d_out;                          // [2*8192*3]

    dim3 grid(NGROUP, JSPLIT);
    lddmm_fused_kernel<<<grid, TI>>>(mom, control_points, out);
}

// round 5
// speedup vs baseline: 1.0894x; 1.0894x over previous
#include <cuda_runtime.h>

// LDDMM Hamiltonian evolve, B=1, N=8192, D=3, sigma=0.1
// out[0 : 3N]   = -dH/dq = 400 * sum_j K_ij * <p_i,p_j> * (q_i - q_j)
// out[3N : 6N]  =  dH/dp = 2   * sum_j K_ij * p_j
// K_ij = exp(-100*|q_i-q_j|^2) = exp2(C*d2), C = -100*log2(e)
//
// d2 expanded via norms (coords centered at 0.5):
//   K_ij = E_i * exp2( s_j + cq_j . m2q_i ),  E_i = exp2(C*|cq_i|^2)
// 14 packed f32x2 fma-pipe ops per 2 j-points.

#define NPTS 8192
#define TI 128             // threads per CTA (i-tile)
#define JSPLIT 16          // j-dimension partitions
#define JC (NPTS / JSPLIT) // 512 j per CTA
#define JPAIRS (JC / 2)    // 256 packed pairs
#define HALFSZ (NPTS * 3)  // floats per output half
#define PLANE (2 * HALFSZ) // 49152 floats per js-plane

// Deterministic two-pass reduction scratch: [JSPLIT][PLANE]
__device__ float g_part[(size_t)JSPLIT * PLANE];

typedef unsigned long long u64;

__device__ __forceinline__ u64 pack2(float lo, float hi) {
    u64 r; asm("mov.b64 %0, {%1, %2};" : "=l"(r) : "f"(lo), "f"(hi)); return r;
}
__device__ __forceinline__ void unpack2(u64 v, float& lo, float& hi) {
    asm("mov.b64 {%0, %1}, %2;" : "=f"(lo), "=f"(hi) : "l"(v));
}
__device__ __forceinline__ u64 fma2(u64 a, u64 b, u64 c) {
    u64 r; asm("fma.rn.f32x2 %0, %1, %2, %3;" : "=l"(r) : "l"(a), "l"(b), "l"(c)); return r;
}
__device__ __forceinline__ u64 add2(u64 a, u64 b) {
    u64 r; asm("add.rn.f32x2 %0, %1, %2;" : "=l"(r) : "l"(a), "l"(b)); return r;
}
__device__ __forceinline__ u64 mul2(u64 a, u64 b) {
    u64 r; asm("mul.rn.f32x2 %0, %1, %2;" : "=l"(r) : "l"(a), "l"(b)); return r;
}
__device__ __forceinline__ u64 ex2_2(u64 x) {
    u64 r;
    asm("{\n\t"
        ".reg .f32 l, h;\n\t"
        "mov.b64 {l, h}, %1;\n\t"
        "ex2.approx.ftz.f32 l, l;\n\t"
        "ex2.approx.ftz.f32 h, h;\n\t"
        "mov.b64 %0, {l, h};\n\t"
        "}" : "=l"(r) : "l"(x));
    return r;
}
__device__ __forceinline__ float fast_ex2(float x) {
    float y; asm("ex2.approx.ftz.f32 %0, %1;" : "=f"(y) : "f"(x)); return y;
}

#define CKER (-144.26950408889634f)   // -100 * log2(e)

__global__ __launch_bounds__(TI, 7)   // 7 CTAs/SM covers 1024-CTA grid in one
                                      // wave; ~72 regs for load pipelining
void lddmm_partial_kernel(const float* __restrict__ mom,
                          const float* __restrict__ q) {
    // Per j-pair: [cqx|cqy][cqz|sj][pjx|pjy] as 3x LDS.128, pjz separate LDS.64
    __shared__ __align__(16) u64 s[JPAIRS * 6];
    __shared__ __align__(16) u64 sz[JPAIRS];

    const int js = blockIdx.y;
    const int jbase = js * JC;

    for (int p = threadIdx.x; p < JPAIRS; p += TI) {
        const int j0 = jbase + 2 * p;
        const int j1 = j0 + 1;
        const float x0 = q[j0 * 3 + 0] - 0.5f, x1 = q[j1 * 3 + 0] - 0.5f;
        const float y0 = q[j0 * 3 + 1] - 0.5f, y1 = q[j1 * 3 + 1] - 0.5f;
        const float z0 = q[j0 * 3 + 2] - 0.5f, z1 = q[j1 * 3 + 2] - 0.5f;
        const float s0 = CKER * (x0 * x0 + y0 * y0 + z0 * z0);
        const float s1 = CKER * (x1 * x1 + y1 * y1 + z1 * z1);
        s[p * 6 + 0] = pack2(x0, x1);
        s[p * 6 + 1] = pack2(y0, y1);
        s[p * 6 + 2] = pack2(z0, z1);
        s[p * 6 + 3] = pack2(s0, s1);
        s[p * 6 + 4] = pack2(mom[j0 * 3 + 0], mom[j1 * 3 + 0]);
        s[p * 6 + 5] = pack2(mom[j0 * 3 + 1], mom[j1 * 3 + 1]);
        sz[p]        = pack2(mom[j0 * 3 + 2], mom[j1 * 3 + 2]);
    }
    __syncthreads();

    const int i = blockIdx.x * TI + threadIdx.x;
    const float cqx = q[i * 3 + 0] - 0.5f;
    const float cqy = q[i * 3 + 1] - 0.5f;
    const float cqz = q[i * 3 + 2] - 0.5f;
    const float px = mom[i * 3 + 0], py = mom[i * 3 + 1], pz = mom[i * 3 + 2];

    const float m2x = -2.0f * CKER * cqx;
    const float m2y = -2.0f * CKER * cqy;
    const float m2z = -2.0f * CKER * cqz;
    const u64 M2X = pack2(m2x, m2x), M2Y = pack2(m2y, m2y), M2Z = pack2(m2z, m2z);
    const u64 PXX = pack2(px, px), PYY = pack2(py, py), PZZ = pack2(pz, pz);

    u64 B0 = 0, B1 = 0, B2 = 0;  // sum K' * p_j
    u64 A0 = 0, A1 = 0, A2 = 0;  // sum w' * cq_j
    u64 W  = 0;                   // sum w'

#pragma unroll 4
    for (int p = 0; p < JPAIRS; p++) {
        const ulonglong2 w0 = *reinterpret_cast<const ulonglong2*>(&s[p * 6 + 0]);
        const ulonglong2 w1 = *reinterpret_cast<const ulonglong2*>(&s[p * 6 + 2]);
        const ulonglong2 w2 = *reinterpret_cast<const ulonglong2*>(&s[p * 6 + 4]);
        const u64 mz = sz[p];
        const u64 jx = w0.x, jy = w0.y, jz = w1.x, sj = w1.y;
        const u64 mx = w2.x, my = w2.y;

        u64 t = fma2(jx, M2X, sj);
        t = fma2(jy, M2Y, t);
        t = fma2(jz, M2Z, t);
        const u64 K = ex2_2(t);

        const u64 pd = fma2(PXX, mx, fma2(PYY, my, mul2(PZZ, mz)));

        B0 = fma2(K, mx, B0);
        B1 = fma2(K, my, B1);
        B2 = fma2(K, mz, B2);

        const u64 w = mul2(K, pd);
        W  = add2(W, w);
        A0 = fma2(w, jx, A0);
        A1 = fma2(w, jy, A1);
        A2 = fma2(w, jz, A2);
    }

    const float Ei = fast_ex2(CKER * (cqx * cqx + cqy * cqy + cqz * cqz));
    const float eq = 400.0f * Ei;
    const float ep = 2.0f * Ei;

    float l, h, Ws, A0s, A1s, A2s, B0s, B1s, B2s;
    unpack2(W,  l, h); Ws  = l + h;
    unpack2(A0, l, h); A0s = l + h;
    unpack2(A1, l, h); A1s = l + h;
    unpack2(A2, l, h); A2s = l + h;
    unpack2(B0, l, h); B0s = l + h;
    unpack2(B1, l, h); B1s = l + h;
    unpack2(B2, l, h); B2s = l + h;

    float* gp = &g_part[(size_t)js * PLANE];
    gp[i * 3 + 0] = eq * fmaf(Ws, cqx, -A0s);
    gp[i * 3 + 1] = eq * fmaf(Ws, cqy, -A1s);
    gp[i * 3 + 2] = eq * fmaf(Ws, cqz, -A2s);
    gp[HALFSZ + i * 3 + 0] = ep * B0s;
    gp[HALFSZ + i * 3 + 1] = ep * B1s;
    gp[HALFSZ + i * 3 + 2] = ep * B2s;
}

// Vectorized reduce: one float4 per thread, 16 LDG.128 (MLP=16) + 1 STG.128.
__global__ __launch_bounds__(128)
void lddmm_reduce_kernel(float* __restrict__ out) {
    const int v = blockIdx.x * blockDim.x + threadIdx.x;   // float4 index
    if (v >= PLANE / 4) return;
    const float4* gp = reinterpret_cast<const float4*>(g_part);
    float4 acc = make_float4(0.f, 0.f, 0.f, 0.f);
#pragma unroll
    for (int js = 0; js < JSPLIT; js++) {
        const float4 r = gp[(size_t)js * (PLANE / 4) + v];
        acc.x += r.x; acc.y += r.y; acc.z += r.z; acc.w += r.w;
    }
    reinterpret_cast<float4*>(out)[v] = acc;
}

extern "C" void kernel_launch(void* const* d_in, const int* in_sizes, int n_in,
                              void* d_out, int out_size) {
    const float* mom = (const float*)d_in[0];            // [1,8192,3]
    const float* control_points = (const float*)d_in[1]; // [1,8192,3]
    float* out = (float*)d_out;                          // [2*8192*3]

    dim3 grid(NPTS / TI, JSPLIT);
    lddmm_partial_kernel<<<grid, TI>>>(mom, control_points);

    lddmm_reduce_kernel<<<(PLANE / 4) / 128, 128>>>(out);
}

// round 6
// speedup vs baseline: 1.0987x; 1.0085x over previous
#include <cuda_runtime.h>

// LDDMM Hamiltonian evolve, B=1, N=8192, D=3, sigma=0.1
// out[0 : 3N]   = -dH/dq = 400 * sum_j K_ij * <p_i,p_j> * (q_i - q_j)
// out[3N : 6N]  =  dH/dp = 2   * sum_j K_ij * p_j
// K_ij = exp(-100*|q_i-q_j|^2) = exp2(C*d2), C = -100*log2(e)
//
// d2 expanded via norms (coords centered at 0.5):
//   K_ij = E_i * exp2( s_j + cq_j . m2q_i ),  E_i = exp2(C*|cq_i|^2)
// 14 packed f32x2 fma-pipe ops per 2 j-points.
// Fusion: zero-init kernel, then each (i,js) CTA atomically adds its
// 6 partials straight into out. No scratch, no reduce kernel.

#define NPTS 8192
#define TI 128             // threads per CTA (i-tile)
#define JSPLIT 16          // j-dimension partitions
#define JC (NPTS / JSPLIT) // 512 j per CTA
#define JPAIRS (JC / 2)    // 256 packed pairs
#define HALFSZ (NPTS * 3)  // floats per output half
#define OUTSZ (2 * HALFSZ) // 49152 floats

typedef unsigned long long u64;

__device__ __forceinline__ u64 pack2(float lo, float hi) {
    u64 r; asm("mov.b64 %0, {%1, %2};" : "=l"(r) : "f"(lo), "f"(hi)); return r;
}
__device__ __forceinline__ void unpack2(u64 v, float& lo, float& hi) {
    asm("mov.b64 {%0, %1}, %2;" : "=f"(lo), "=f"(hi) : "l"(v));
}
__device__ __forceinline__ u64 fma2(u64 a, u64 b, u64 c) {
    u64 r; asm("fma.rn.f32x2 %0, %1, %2, %3;" : "=l"(r) : "l"(a), "l"(b), "l"(c)); return r;
}
__device__ __forceinline__ u64 add2(u64 a, u64 b) {
    u64 r; asm("add.rn.f32x2 %0, %1, %2;" : "=l"(r) : "l"(a), "l"(b)); return r;
}
__device__ __forceinline__ u64 mul2(u64 a, u64 b) {
    u64 r; asm("mul.rn.f32x2 %0, %1, %2;" : "=l"(r) : "l"(a), "l"(b)); return r;
}
__device__ __forceinline__ u64 ex2_2(u64 x) {
    u64 r;
    asm("{\n\t"
        ".reg .f32 l, h;\n\t"
        "mov.b64 {l, h}, %1;\n\t"
        "ex2.approx.ftz.f32 l, l;\n\t"
        "ex2.approx.ftz.f32 h, h;\n\t"
        "mov.b64 %0, {l, h};\n\t"
        "}" : "=l"(r) : "l"(x));
    return r;
}
__device__ __forceinline__ float fast_ex2(float x) {
    float y; asm("ex2.approx.ftz.f32 %0, %1;" : "=f"(y) : "f"(x)); return y;
}

#define CKER (-144.26950408889634f)   // -100 * log2(e)

__global__ __launch_bounds__(128)
void lddmm_zero_kernel(float* __restrict__ out) {
    const int v = blockIdx.x * blockDim.x + threadIdx.x;
    reinterpret_cast<float4*>(out)[v] = make_float4(0.f, 0.f, 0.f, 0.f);
}

__global__ __launch_bounds__(TI, 7)
void lddmm_partial_kernel(const float* __restrict__ mom,
                          const float* __restrict__ q,
                          float* __restrict__ out) {
    // Per j-pair: [cqx|cqy][cqz|sj][pjx|pjy] as 3x LDS.128, pjz separate LDS.64
    __shared__ __align__(16) u64 s[JPAIRS * 6];
    __shared__ __align__(16) u64 sz[JPAIRS];

    const int js = blockIdx.y;
    const int jbase = js * JC;

    for (int p = threadIdx.x; p < JPAIRS; p += TI) {
        const int j0 = jbase + 2 * p;
        const int j1 = j0 + 1;
        const float x0 = q[j0 * 3 + 0] - 0.5f, x1 = q[j1 * 3 + 0] - 0.5f;
        const float y0 = q[j0 * 3 + 1] - 0.5f, y1 = q[j1 * 3 + 1] - 0.5f;
        const float z0 = q[j0 * 3 + 2] - 0.5f, z1 = q[j1 * 3 + 2] - 0.5f;
        const float s0 = CKER * (x0 * x0 + y0 * y0 + z0 * z0);
        const float s1 = CKER * (x1 * x1 + y1 * y1 + z1 * z1);
        s[p * 6 + 0] = pack2(x0, x1);
        s[p * 6 + 1] = pack2(y0, y1);
        s[p * 6 + 2] = pack2(z0, z1);
        s[p * 6 + 3] = pack2(s0, s1);
        s[p * 6 + 4] = pack2(mom[j0 * 3 + 0], mom[j1 * 3 + 0]);
        s[p * 6 + 5] = pack2(mom[j0 * 3 + 1], mom[j1 * 3 + 1]);
        sz[p]        = pack2(mom[j0 * 3 + 2], mom[j1 * 3 + 2]);
    }
    __syncthreads();

    const int i = blockIdx.x * TI + threadIdx.x;
    const float cqx = q[i * 3 + 0] - 0.5f;
    const float cqy = q[i * 3 + 1] - 0.5f;
    const float cqz = q[i * 3 + 2] - 0.5f;
    const float px = mom[i * 3 + 0], py = mom[i * 3 + 1], pz = mom[i * 3 + 2];

    const float m2x = -2.0f * CKER * cqx;
    const float m2y = -2.0f * CKER * cqy;
    const float m2z = -2.0f * CKER * cqz;
    const u64 M2X = pack2(m2x, m2x), M2Y = pack2(m2y, m2y), M2Z = pack2(m2z, m2z);
    const u64 PXX = pack2(px, px), PYY = pack2(py, py), PZZ = pack2(pz, pz);

    u64 B0 = 0, B1 = 0, B2 = 0;  // sum K' * p_j
    u64 A0 = 0, A1 = 0, A2 = 0;  // sum w' * cq_j
    u64 W  = 0;                   // sum w'

#pragma unroll 4
    for (int p = 0; p < JPAIRS; p++) {
        const ulonglong2 w0 = *reinterpret_cast<const ulonglong2*>(&s[p * 6 + 0]);
        const ulonglong2 w1 = *reinterpret_cast<const ulonglong2*>(&s[p * 6 + 2]);
        const ulonglong2 w2 = *reinterpret_cast<const ulonglong2*>(&s[p * 6 + 4]);
        const u64 mz = sz[p];
        const u64 jx = w0.x, jy = w0.y, jz = w1.x, sj = w1.y;
        const u64 mx = w2.x, my = w2.y;

        u64 t = fma2(jx, M2X, sj);
        t = fma2(jy, M2Y, t);
        t = fma2(jz, M2Z, t);
        const u64 K = ex2_2(t);

        const u64 pd = fma2(PXX, mx, fma2(PYY, my, mul2(PZZ, mz)));

        B0 = fma2(K, mx, B0);
        B1 = fma2(K, my, B1);
        B2 = fma2(K, mz, B2);

        const u64 w = mul2(K, pd);
        W  = add2(W, w);
        A0 = fma2(w, jx, A0);
        A1 = fma2(w, jy, A1);
        A2 = fma2(w, jz, A2);
    }

    const float Ei = fast_ex2(CKER * (cqx * cqx + cqy * cqy + cqz * cqz));
    const float eq = 400.0f * Ei;
    const float ep = 2.0f * Ei;

    float l, h, Ws, A0s, A1s, A2s, B0s, B1s, B2s;
    unpack2(W,  l, h); Ws  = l + h;
    unpack2(A0, l, h); A0s = l + h;
    unpack2(A1, l, h); A1s = l + h;
    unpack2(A2, l, h); A2s = l + h;
    unpack2(B0, l, h); B0s = l + h;
    unpack2(B1, l, h); B1s = l + h;
    unpack2(B2, l, h); B2s = l + h;

    // Fire-and-forget accumulation into out (16 adders per address).
    atomicAdd(&out[i * 3 + 0], eq * fmaf(Ws, cqx, -A0s));
    atomicAdd(&out[i * 3 + 1], eq * fmaf(Ws, cqy, -A1s));
    atomicAdd(&out[i * 3 + 2], eq * fmaf(Ws, cqz, -A2s));
    atomicAdd(&out[HALFSZ + i * 3 + 0], ep * B0s);
    atomicAdd(&out[HALFSZ + i * 3 + 1], ep * B1s);
    atomicAdd(&out[HALFSZ + i * 3 + 2], ep * B2s);
}

extern "C" void kernel_launch(void* const* d_in, const int* in_sizes, int n_in,
                              void* d_out, int out_size) {
    const float* mom = (const float*)d_in[0];            // [1,8192,3]
    const float* control_points = (const float*)d_in[1]; // [1,8192,3]
    float* out = (float*)d_out;                          // [2*8192*3]

    lddmm_zero_kernel<<<(OUTSZ / 4) / 128, 128>>>(out);

    dim3 grid(NPTS / TI, JSPLIT);
    lddmm_partial_kernel<<<grid, TI>>>(mom, control_points, out);
}